// round 14
// baseline (speedup 1.0000x reference)
#include <cuda_runtime.h>
#include <cstdint>

// R-MAC over x[32, 2048, 32, 32] -> out[32, 2048].
// 19 static regions (H=W=32): 1x full (32x32), 6x 21x21 (rows {0,5,11} x cols
// {0,11}), 12x 16x16 (rows {0,5,10,16} x cols {0,8,16}).
// Column segments: s1=[0,21) s2=[11,32) s3=[0,16) s4=[8,24) s5=[16,32).
// Row-block decomposition:
//   segs 1,2 (fam B): blocks [0,5)[5,11)[11,16)[16,21)[21,26)[26,32)
//   segs 3,4,5 (fam C): blocks [0,5)[5,10)[10,16)[16,21)[21,26)[26,32)
// Full image = max over bmbuf of segs 1,2 (cols [0,21)u[11,32)=[0,32), all rows).
//
// R14 design: single-shot blocks = maximum phase diversity. Each warp handles
// exactly ONE tile: burst 4 KB via cp.async, wait, consume, write, exit.
// 16 KB ring + ~4.4 KB static -> ~11 independent blocks/SM (44 warps/SM),
// grid 16384 (~10 waves). Load-burst injection becomes quasi-continuous;
// latency hiding is cross-warp, not intra-warp.

#define WPB   4
#define NTILES (32 * 2048)
#define DYN_SMEM (WPB * 4096)

__constant__ int c_start[2][6] = {{0, 5, 11, 16, 21, 26}, {0, 5, 10, 16, 21, 26}};
__constant__ int c_sz6[2][6]   = {{0, 1, 0, 0, 0, 1},     {0, 0, 1, 0, 0, 1}};
__constant__ int c_rbase[19] = {0, 0, 6, 1, 7, 2, 8,
                                12, 18, 24, 13, 19, 25, 14, 20, 26, 15, 21, 27};
__constant__ int c_rcnt4[19] = {0, 1, 1, 1, 1, 1, 1, 0, 0, 0, 0, 0, 0, 0, 0, 0, 0, 0, 0};

__device__ __forceinline__ void cpa16(uint32_t dst_smem, const void* src) {
    asm volatile("cp.async.cg.shared.global [%0], [%1], 16;"
                 :: "r"(dst_smem), "l"(src) : "memory");
}
__device__ __forceinline__ void cpa_commit() {
    asm volatile("cp.async.commit_group;" ::: "memory");
}
__device__ __forceinline__ void cpa_wait_all() {
    asm volatile("cp.async.wait_group 0;" ::: "memory");
}

__global__ __launch_bounds__(32 * WPB)
void rmac_kernel(const float* __restrict__ x, float* __restrict__ out) {
    extern __shared__ float4 ring[];      // [WPB][256] float4 = 16 KB
    __shared__ float segm[WPB][32 * 7];   // per-row segment maxes, stride 7
    __shared__ float bmbuf[WPB][32];      // 30 (seg,block) maxes
    __shared__ float rsum[WPB][20];       // region maxes for the final sum

    const int wib  = threadIdx.x >> 5;
    const int lane = threadIdx.x & 31;
    const size_t t = (size_t)blockIdx.x * WPB + wib;   // this warp's tile

    const float4* __restrict__ src =
        reinterpret_cast<const float4*>(x) + t * 256;
    const uint32_t sb =
        (uint32_t)__cvta_generic_to_shared(ring) + (uint32_t)(wib * 4096);

    // Write mapping: lane l, op k holds tile quad (k*32+l) = row 4k+(l>>3),
    // 16B-group c=l&7. Store XOR-swizzled: group slot c ^ (row&7).
    const int wrow_a = lane >> 3;
    const int wc     = lane & 7;

    // ---- Burst: this warp's entire tile, one commit group ----
#pragma unroll
    for (int k = 0; k < 8; k++) {
        const int row = 4 * k + wrow_a;
        const uint32_t dst = sb + (uint32_t)((row * 8 + (wc ^ (row & 7))) * 16);
        cpa16(dst, src + k * 32 + lane);
    }
    cpa_commit();

    cpa_wait_all();
    __syncwarp();                         // publish all lanes' copies

    // ---- Row reduce straight from swizzled smem (lane = row) ----
    const int r  = lane;
    const int rx = r & 7;
    const float4* B = ring + (size_t)wib * 256 + r * 8;
    float4 q[8];
#pragma unroll
    for (int g = 0; g < 8; g++) q[g] = B[g ^ rx];      // conflict-free LDS.128
    float m[8];
#pragma unroll
    for (int g = 0; g < 8; g++)
        m[g] = fmaxf(fmaxf(q[g].x, q[g].y), fmaxf(q[g].z, q[g].w));
    const float r11 = q[2].w;             // col 11
    const float r20 = q[5].x;             // col 20

    const float s3 = fmaxf(fmaxf(m[0], m[1]), fmaxf(m[2], m[3]));  // [0,16)
    const float s4 = fmaxf(fmaxf(m[2], m[3]), fmaxf(m[4], m[5]));  // [8,24)
    const float s5 = fmaxf(fmaxf(m[4], m[5]), fmaxf(m[6], m[7]));  // [16,32)
    const float s1 = fmaxf(s3, fmaxf(m[4], r20));                  // [0,21)
    const float s2 = fmaxf(r11, fmaxf(m[3], s5));                  // [11,32)

    float* sd = segm[wib] + r * 7;        // stride 7: conflict-free
    sd[1] = s1; sd[2] = s2; sd[3] = s3; sd[4] = s4; sd[5] = s5;
    __syncwarp();

    // ---- 30 (segment, row-block) maxes ----
    if (lane < 30) {
        const int s   = 1 + lane / 6;
        const int blk = lane % 6;
        const int fam = (s >= 3);
        const int st  = c_start[fam][blk];
        const float* sp = segm[wib] + s;
        float bm = sp[st * 7];
#pragma unroll
        for (int qq = 1; qq < 5; qq++) bm = fmaxf(bm, sp[(st + qq) * 7]);
        if (c_sz6[fam][blk]) bm = fmaxf(bm, sp[(st + 5) * 7]);
        bmbuf[wib][lane] = bm;
    }
    __syncwarp();

    // ---- Region maxes into rsum (lanes 0/19 zero-pad) ----
    if (lane >= 1 && lane < 19) {
        const float* bp = bmbuf[wib];
        const int base = c_rbase[lane];
        float mm = fmaxf(fmaxf(bp[base], bp[base + 1]), bp[base + 2]);
        if (c_rcnt4[lane]) mm = fmaxf(mm, bp[base + 3]);
        rsum[wib][lane] = mm;
    } else if (lane == 19) {
        rsum[wib][19] = 0.0f;
    } else if (lane == 0) {
        rsum[wib][0] = 0.0f;
    }
    __syncwarp();

    // ---- Lane 0: full-image max + sum of 19 regions ----
    if (lane == 0) {
        const float4 b0 = *reinterpret_cast<const float4*>(&bmbuf[wib][0]);
        const float4 b1 = *reinterpret_cast<const float4*>(&bmbuf[wib][4]);
        const float4 b2 = *reinterpret_cast<const float4*>(&bmbuf[wib][8]);
        float full = fmaxf(fmaxf(fmaxf(b0.x, b0.y), fmaxf(b0.z, b0.w)),
                           fmaxf(fmaxf(b1.x, b1.y), fmaxf(b1.z, b1.w)));
        full = fmaxf(full, fmaxf(fmaxf(b2.x, b2.y), fmaxf(b2.z, b2.w)));

        const float4 q0 = *reinterpret_cast<const float4*>(&rsum[wib][0]);
        const float4 q1 = *reinterpret_cast<const float4*>(&rsum[wib][4]);
        const float4 q2 = *reinterpret_cast<const float4*>(&rsum[wib][8]);
        const float4 q3 = *reinterpret_cast<const float4*>(&rsum[wib][12]);
        const float4 q4 = *reinterpret_cast<const float4*>(&rsum[wib][16]);
        float acc = ((q0.x + q0.y) + (q0.z + q0.w))
                  + ((q1.x + q1.y) + (q1.z + q1.w))
                  + ((q2.x + q2.y) + (q2.z + q2.w))
                  + ((q3.x + q3.y) + (q3.z + q3.w))
                  + ((q4.x + q4.y) + (q4.z + q4.w))
                  + full;
        out[t] = acc;
    }
}

extern "C" void kernel_launch(void* const* d_in, const int* in_sizes, int n_in,
                              void* d_out, int out_size) {
    const float* x = (const float*)d_in[0];
    float* out = (float*)d_out;
    (void)in_sizes; (void)n_in; (void)out_size;
    cudaFuncSetAttribute(rmac_kernel,
                         cudaFuncAttributeMaxDynamicSharedMemorySize, DYN_SMEM);
    rmac_kernel<<<NTILES / WPB, 32 * WPB, DYN_SMEM>>>(x, out);
}